// round 1
// baseline (speedup 1.0000x reference)
#include <cuda_runtime.h>
#include <cuda_bf16.h>

// Problem constants
#define INPUT_DIM 4
#define H1 64          // hidden_dim
#define H2 32          // latent_dim
#define BATCH 64
#define SEQ 4096

#define G1 (4*H1)      // 256 layer-1 gates
#define G2 (4*H2)      // 128 layer-2 gates
#define NTHREADS (G1 + G2)  // 384

__device__ __forceinline__ float sigmoid_f(float x) {
    return __fdividef(1.0f, 1.0f + __expf(-x));
}
__device__ __forceinline__ float tanh_f(float x) {
    // tanh(x) = 2*sigmoid(2x) - 1
    return __fmaf_rn(2.0f, __fdividef(1.0f, 1.0f + __expf(-2.0f * x)), -1.0f);
}

__global__ void __launch_bounds__(NTHREADS, 1)
lstm2_kernel(const float* __restrict__ x,
             const float* __restrict__ W_ih1, const float* __restrict__ W_hh1,
             const float* __restrict__ b_ih1, const float* __restrict__ b_hh1,
             const float* __restrict__ W_ih2, const float* __restrict__ W_hh2,
             const float* __restrict__ b_ih2, const float* __restrict__ b_hh2,
             float* __restrict__ out)
{
    const int b   = blockIdx.x;      // batch element
    const int tid = threadIdx.x;

    __shared__ __align__(16) float h1_sh[H1];
    __shared__ __align__(16) float h2_sh[H2];
    __shared__ __align__(16) float g1_sh[G1];
    __shared__ __align__(16) float g2_sh[G2];

    // -------- per-thread register weights --------
    // tid <  256 : layer-1 gate g = tid.   w[0..63] = W_hh1[g,:], w[64..67] = W_ih1[g,:]
    // tid >= 256 : layer-2 gate g = tid-256. w[0..63] = W_ih2[g,:], w[64..95] = W_hh2[g,:]
    float w[96];
    float bias;
    if (tid < G1) {
        const int g = tid;
        #pragma unroll
        for (int k = 0; k < 64; ++k) w[k] = W_hh1[g * 64 + k];
        #pragma unroll
        for (int k = 0; k < 4; ++k)  w[64 + k] = W_ih1[g * 4 + k];
        #pragma unroll
        for (int k = 0; k < 28; ++k) w[68 + k] = 0.0f;
        bias = b_ih1[g] + b_hh1[g];
    } else {
        const int g = tid - G1;
        #pragma unroll
        for (int k = 0; k < 64; ++k) w[k] = W_ih2[g * 64 + k];
        #pragma unroll
        for (int k = 0; k < 32; ++k) w[64 + k] = W_hh2[g * 32 + k];
        bias = b_ih2[g] + b_hh2[g];
    }

    // per-thread cell state registers
    float c1 = 0.0f;   // valid in tid < 64
    float c2 = 0.0f;   // valid in 64 <= tid < 96

    const float* xb = x + (size_t)b * SEQ * INPUT_DIM;
    float* outb = out + (size_t)b * SEQ * H2;

    // -------- prologue: gates1(0) with h1(-1)=0; init h2 --------
    if (tid < G1) {
        const float4 xv = *reinterpret_cast<const float4*>(xb);
        g1_sh[tid] = bias + w[64]*xv.x + w[65]*xv.y + w[66]*xv.z + w[67]*xv.w;
    }
    if (tid >= 64 && tid < 96) h2_sh[tid - 64] = 0.0f;
    __syncthreads();
    if (tid < H1) {
        const float gi = g1_sh[tid], gf = g1_sh[H1 + tid],
                    gg = g1_sh[2*H1 + tid], go = g1_sh[3*H1 + tid];
        const float iv = sigmoid_f(gi), fv = sigmoid_f(gf),
                    gv = tanh_f(gg),    ov = sigmoid_f(go);
        c1 = fv * c1 + iv * gv;
        h1_sh[tid] = ov * tanh_f(c1);
    }
    __syncthreads();

    // -------- main loop --------
    // iteration t:  phase A: layer1 gates(t+1) from h1(t)  ||  layer2 gates2(t) from h1(t),h2(t-1)
    //               phase B: update h1(t+1), c1  ||  update h2(t), c2, store out(t)
    for (int t = 0; t < SEQ; ++t) {
        // ---- phase A ----
        if (tid < G1) {
            if (t + 1 < SEQ) {
                const float4 xv = *reinterpret_cast<const float4*>(xb + (size_t)(t + 1) * INPUT_DIM);
                float a0 = bias + w[64]*xv.x + w[65]*xv.y + w[66]*xv.z + w[67]*xv.w;
                float a1 = 0.0f, a2 = 0.0f, a3 = 0.0f;
                const float4* h1v = reinterpret_cast<const float4*>(h1_sh);
                #pragma unroll
                for (int kk = 0; kk < 16; ++kk) {
                    const float4 hv = h1v[kk];
                    a0 = __fmaf_rn(w[4*kk+0], hv.x, a0);
                    a1 = __fmaf_rn(w[4*kk+1], hv.y, a1);
                    a2 = __fmaf_rn(w[4*kk+2], hv.z, a2);
                    a3 = __fmaf_rn(w[4*kk+3], hv.w, a3);
                }
                g1_sh[tid] = (a0 + a1) + (a2 + a3);
            }
        } else {
            const int g = tid - G1;
            float a0 = bias, a1 = 0.0f, a2 = 0.0f, a3 = 0.0f;
            const float4* h1v = reinterpret_cast<const float4*>(h1_sh);
            #pragma unroll
            for (int kk = 0; kk < 16; ++kk) {
                const float4 hv = h1v[kk];
                a0 = __fmaf_rn(w[4*kk+0], hv.x, a0);
                a1 = __fmaf_rn(w[4*kk+1], hv.y, a1);
                a2 = __fmaf_rn(w[4*kk+2], hv.z, a2);
                a3 = __fmaf_rn(w[4*kk+3], hv.w, a3);
            }
            const float4* h2v = reinterpret_cast<const float4*>(h2_sh);
            #pragma unroll
            for (int kk = 0; kk < 8; ++kk) {
                const float4 hv = h2v[kk];
                a0 = __fmaf_rn(w[64+4*kk+0], hv.x, a0);
                a1 = __fmaf_rn(w[64+4*kk+1], hv.y, a1);
                a2 = __fmaf_rn(w[64+4*kk+2], hv.z, a2);
                a3 = __fmaf_rn(w[64+4*kk+3], hv.w, a3);
            }
            g2_sh[g] = (a0 + a1) + (a2 + a3);
        }
        __syncthreads();

        // ---- phase B ----
        if (tid < H1) {
            if (t + 1 < SEQ) {
                const float gi = g1_sh[tid], gf = g1_sh[H1 + tid],
                            gg = g1_sh[2*H1 + tid], go = g1_sh[3*H1 + tid];
                const float iv = sigmoid_f(gi), fv = sigmoid_f(gf),
                            gv = tanh_f(gg),    ov = sigmoid_f(go);
                c1 = fv * c1 + iv * gv;
                h1_sh[tid] = ov * tanh_f(c1);
            }
        } else if (tid < 96) {
            const int j = tid - 64;
            const float gi = g2_sh[j], gf = g2_sh[H2 + j],
                        gg = g2_sh[2*H2 + j], go = g2_sh[3*H2 + j];
            const float iv = sigmoid_f(gi), fv = sigmoid_f(gf),
                        gv = tanh_f(gg),    ov = sigmoid_f(go);
            c2 = fv * c2 + iv * gv;
            const float h2 = ov * tanh_f(c2);
            h2_sh[j] = h2;
            outb[(size_t)t * H2 + j] = h2;
        }
        __syncthreads();
    }
}

extern "C" void kernel_launch(void* const* d_in, const int* in_sizes, int n_in,
                              void* d_out, int out_size) {
    const float* x     = (const float*)d_in[0];
    const float* W_ih1 = (const float*)d_in[1];
    const float* W_hh1 = (const float*)d_in[2];
    const float* b_ih1 = (const float*)d_in[3];
    const float* b_hh1 = (const float*)d_in[4];
    const float* W_ih2 = (const float*)d_in[5];
    const float* W_hh2 = (const float*)d_in[6];
    const float* b_ih2 = (const float*)d_in[7];
    const float* b_hh2 = (const float*)d_in[8];
    float* out = (float*)d_out;

    lstm2_kernel<<<BATCH, NTHREADS>>>(x, W_ih1, W_hh1, b_ih1, b_hh1,
                                      W_ih2, W_hh2, b_ih2, b_hh2, out);
}